// round 8
// baseline (speedup 1.0000x reference)
#include <cuda_runtime.h>
#include <cstdint>

// Problem constants (B=4, L=2048, H=16, D=64 — fixed by the dataset)
#define Bc 4
#define Hc 16
#define Lc 2048
#define Dc 64
#define BM 256
#define BN 64
#define NT 512
#define NW 16

// Smem:
//   K/V double-buffered: uint2[2 buf][2 arr][64 key][KSu d] (tf32 hi,lo pairs)
//   P: per-warp float[16][PSf]
#define KSu 68
#define PSf 68
#define KVu (64 * KSu)                                   // uint2 per K or V tile
#define SMEM_BYTES (4 * KVu * 8 + NW * 16 * PSf * 4)     // 208,896 B

__device__ __forceinline__ void tf32_split(float x, uint32_t& hi, uint32_t& lo) {
    uint32_t h;
    asm("cvt.rna.tf32.f32 %0, %1;" : "=r"(h) : "f"(x));
    hi = h;
    float lf = x - __uint_as_float(h);
    asm("cvt.rna.tf32.f32 %0, %1;" : "=r"(lo) : "f"(lf));
}
__device__ __forceinline__ uint32_t tf32_rna(float x) {
    uint32_t h;
    asm("cvt.rna.tf32.f32 %0, %1;" : "=r"(h) : "f"(x));
    return h;
}
__device__ __forceinline__ void mma8(float* d,
                                     uint32_t a0, uint32_t a1, uint32_t a2, uint32_t a3,
                                     uint32_t b0, uint32_t b1) {
    asm("mma.sync.aligned.m16n8k8.row.col.f32.tf32.tf32.f32 "
        "{%0,%1,%2,%3},{%4,%5,%6,%7},{%8,%9},{%0,%1,%2,%3};"
        : "+f"(d[0]), "+f"(d[1]), "+f"(d[2]), "+f"(d[3])
        : "r"(a0), "r"(a1), "r"(a2), "r"(a3), "r"(b0), "r"(b1));
}

__device__ __forceinline__ void split_store8(uint2* kd, uint2* vd,
                                             float4 kv, float4 vv) {
    uint32_t hi, lo;
    tf32_split(kv.x, hi, lo); kd[0] = make_uint2(hi, lo);
    tf32_split(kv.y, hi, lo); kd[1] = make_uint2(hi, lo);
    tf32_split(kv.z, hi, lo); kd[2] = make_uint2(hi, lo);
    tf32_split(kv.w, hi, lo); kd[3] = make_uint2(hi, lo);
    tf32_split(vv.x, hi, lo); vd[0] = make_uint2(hi, lo);
    tf32_split(vv.y, hi, lo); vd[1] = make_uint2(hi, lo);
    tf32_split(vv.z, hi, lo); vd[2] = make_uint2(hi, lo);
    tf32_split(vv.w, hi, lo); vd[3] = make_uint2(hi, lo);
}

__global__ void __launch_bounds__(NT, 1)
logsparse_flash_tc8_kernel(const float* __restrict__ Q,
                           const float* __restrict__ K,
                           const float* __restrict__ V,
                           float* __restrict__ O) {
    extern __shared__ char smc[];
    uint2* KV = (uint2*)smc;                 // [2 buf][K tile | V tile]
    float* Pa = (float*)(KV + 4 * KVu);      // NW x [16][PSf]

    // Heavy blocks (large m) first: flatten triangular imbalance.
    const int m  = (int)gridDim.x - 1 - (int)blockIdx.x;
    const int bh = blockIdx.y;
    const int b  = bh >> 4;
    const int h  = bh & 15;

    const int tid  = threadIdx.x;
    const int wid  = tid >> 5;
    const int lane = tid & 31;
    const int g    = lane >> 2;
    const int tg   = lane & 3;

    float* Pw = Pa + wid * (16 * PSf);
    const int R0      = wid * 16;
    const int gRowA   = m * BM + R0 + g;
    const int gRowB   = gRowA + 8;
    const int wRowMax = m * BM + R0 + 15;    // lane-uniform warp row bound

    const size_t rs = (size_t)Hc * Dc;       // 1024 floats between seq positions
    const float* Qg = Q + ((size_t)b * Lc + (size_t)m * BM) * rs + (size_t)h * Dc;
    const float* Kg = K + (size_t)b * Lc * rs + (size_t)h * Dc;
    const float* Vg = V + (size_t)b * Lc * rs + (size_t)h * Dc;

    // Per-thread load coordinates (2 iters cover a 64x64 tile with 512 threads)
    const int lr0 = tid >> 4, lc40 = tid & 15;            // it = 0
    const int lr1 = (tid + NT) >> 4, lc41 = (tid + NT) & 15;  // it = 1

    // ---- Q fragments once, pre-scaled by log2(e) (exp -> exp2) ----
    const float LOG2E = 1.4426950408889634f;
    float qf[8][4];
#pragma unroll
    for (int cc = 0; cc < 8; ++cc) {
        int k0 = 8 * cc + tg;
        qf[cc][0] = Qg[(size_t)(R0 + g)     * rs + k0]     * LOG2E;
        qf[cc][1] = Qg[(size_t)(R0 + g + 8) * rs + k0]     * LOG2E;
        qf[cc][2] = Qg[(size_t)(R0 + g)     * rs + k0 + 4] * LOG2E;
        qf[cc][3] = Qg[(size_t)(R0 + g + 8) * rs + k0 + 4] * LOG2E;
    }

    // ---- State (log2 domain) + O accumulators ----
    float o[8][4];
    float mA = -1e30f, mB = -1e30f, lA = 0.f, lB = 0.f;
#pragma unroll
    for (int j = 0; j < 8; ++j) { o[j][0] = o[j][1] = o[j][2] = o[j][3] = 0.f; }

    const int nend = (m * BM + BM - 1) / BN;   // 4m+3

    // ---- Preload tile 0 into buffer 0 ----
    {
        float4 k0 = *(const float4*)(Kg + (size_t)lr0 * rs + lc40 * 4);
        float4 v0 = *(const float4*)(Vg + (size_t)lr0 * rs + lc40 * 4);
        float4 k1 = *(const float4*)(Kg + (size_t)lr1 * rs + lc41 * 4);
        float4 v1 = *(const float4*)(Vg + (size_t)lr1 * rs + lc41 * 4);
        split_store8(KV + lr0 * KSu + lc40 * 4, KV + KVu + lr0 * KSu + lc40 * 4, k0, v0);
        split_store8(KV + lr1 * KSu + lc41 * 4, KV + KVu + lr1 * KSu + lc41 * 4, k1, v1);
    }
    __syncthreads();

    for (int n = 0; n <= nend; ++n) {
        const uint2* KHc = KV + (n & 1) * 2 * KVu;
        const uint2* VHc = KHc + KVu;
        const int nBase = n * BN;

        // ---- Prefetch next tile's gmem into registers (latency hides under mma) ----
        float4 kp0, vp0, kp1, vp1;
        const bool pre = (n < nend);
        if (pre) {
            const size_t nb = (size_t)(nBase + BN);
            kp0 = *(const float4*)(Kg + (nb + lr0) * rs + lc40 * 4);
            vp0 = *(const float4*)(Vg + (nb + lr0) * rs + lc40 * 4);
            kp1 = *(const float4*)(Kg + (nb + lr1) * rs + lc41 * 4);
            vp1 = *(const float4*)(Vg + (nb + lr1) * rs + lc41 * 4);
        }

        if (nBase <= wRowMax) {   // warp has visible columns (uniform predicate)
            // ---- S = Q K^T via 3xTF32 mma ----
            float s[8][4];
#pragma unroll
            for (int j = 0; j < 8; ++j) { s[j][0] = s[j][1] = s[j][2] = s[j][3] = 0.f; }

#pragma unroll
            for (int cc = 0; cc < 8; ++cc) {
                uint32_t qh[4], ql[4];
#pragma unroll
                for (int e = 0; e < 4; ++e) tf32_split(qf[cc][e], qh[e], ql[e]);
#pragma unroll
                for (int j = 0; j < 8; ++j) {
                    uint2 k0 = KHc[(8 * j + g) * KSu + 8 * cc + tg];
                    uint2 k1 = KHc[(8 * j + g) * KSu + 8 * cc + tg + 4];
                    mma8(s[j], qh[0], qh[1], qh[2], qh[3], k0.x, k1.x);
                    mma8(s[j], ql[0], ql[1], ql[2], ql[3], k0.x, k1.x);
                    mma8(s[j], qh[0], qh[1], qh[2], qh[3], k0.y, k1.y);
                }
            }

            // ---- Causal mask (only blocks touching the diagonal) ----
            if (nBase + BN - 1 > m * BM + R0) {
#pragma unroll
                for (int j = 0; j < 8; ++j) {
                    int c0 = nBase + 8 * j + 2 * tg;
                    if (c0     > gRowA) s[j][0] = -1e30f;
                    if (c0 + 1 > gRowA) s[j][1] = -1e30f;
                    if (c0     > gRowB) s[j][2] = -1e30f;
                    if (c0 + 1 > gRowB) s[j][3] = -1e30f;
                }
            }

            // ---- Online softmax (log2 domain), stage tf32-rounded P ----
            float tA = s[0][0], tB = s[0][2];
#pragma unroll
            for (int j = 0; j < 8; ++j) {
                tA = fmaxf(tA, fmaxf(s[j][0], s[j][1]));
                tB = fmaxf(tB, fmaxf(s[j][2], s[j][3]));
            }
            tA = fmaxf(tA, __shfl_xor_sync(0xffffffffu, tA, 1));
            tA = fmaxf(tA, __shfl_xor_sync(0xffffffffu, tA, 2));
            tB = fmaxf(tB, __shfl_xor_sync(0xffffffffu, tB, 1));
            tB = fmaxf(tB, __shfl_xor_sync(0xffffffffu, tB, 2));
            float mnA = fmaxf(mA, tA), mnB = fmaxf(mB, tB);
            float scA = exp2f(mA - mnA), scB = exp2f(mB - mnB);
            float rsA = 0.f, rsB = 0.f;
#pragma unroll
            for (int j = 0; j < 8; ++j) {
                // exp2, round to tf32 ONCE; the rounded value feeds both the
                // row-sum and the PV mma, so normalization is self-consistent.
                uint32_t p0 = tf32_rna(exp2f(s[j][0] - mnA));
                uint32_t p1 = tf32_rna(exp2f(s[j][1] - mnA));
                uint32_t p2 = tf32_rna(exp2f(s[j][2] - mnB));
                uint32_t p3 = tf32_rna(exp2f(s[j][3] - mnB));
                rsA += __uint_as_float(p0) + __uint_as_float(p1);
                rsB += __uint_as_float(p2) + __uint_as_float(p3);
                int c = 8 * j + 2 * tg;
                *(float2*)(Pw + (g)     * PSf + c) =
                    make_float2(__uint_as_float(p0), __uint_as_float(p1));
                *(float2*)(Pw + (g + 8) * PSf + c) =
                    make_float2(__uint_as_float(p2), __uint_as_float(p3));
            }
            rsA += __shfl_xor_sync(0xffffffffu, rsA, 1);
            rsA += __shfl_xor_sync(0xffffffffu, rsA, 2);
            rsB += __shfl_xor_sync(0xffffffffu, rsB, 1);
            rsB += __shfl_xor_sync(0xffffffffu, rsB, 2);
            lA = lA * scA + rsA;  mA = mnA;
            lB = lB * scB + rsB;  mB = mnB;
#pragma unroll
            for (int j = 0; j < 8; ++j) {
                o[j][0] *= scA; o[j][1] *= scA;
                o[j][2] *= scB; o[j][3] *= scB;
            }
            __syncwarp();

            // ---- O += P V : 2 mma terms (P exact tf32, V hi+lo) ----
#pragma unroll
            for (int cc = 0; cc < 8; ++cc) {
                uint32_t a0 = __float_as_uint(Pw[(g)     * PSf + 8 * cc + tg]);
                uint32_t a1 = __float_as_uint(Pw[(g + 8) * PSf + 8 * cc + tg]);
                uint32_t a2 = __float_as_uint(Pw[(g)     * PSf + 8 * cc + tg + 4]);
                uint32_t a3 = __float_as_uint(Pw[(g + 8) * PSf + 8 * cc + tg + 4]);
#pragma unroll
                for (int j = 0; j < 8; ++j) {
                    uint2 v0 = VHc[(8 * cc + tg)     * KSu + 8 * j + g];
                    uint2 v1 = VHc[(8 * cc + tg + 4) * KSu + 8 * j + g];
                    mma8(o[j], a0, a1, a2, a3, v0.x, v1.x);
                    mma8(o[j], a0, a1, a2, a3, v0.y, v1.y);
                }
            }
        }

        // ---- Split + store the prefetched tile into the other buffer ----
        if (pre) {
            uint2* kd = KV + ((n + 1) & 1) * 2 * KVu;
            uint2* vd = kd + KVu;
            split_store8(kd + lr0 * KSu + lc40 * 4, vd + lr0 * KSu + lc40 * 4, kp0, vp0);
            split_store8(kd + lr1 * KSu + lc41 * 4, vd + lr1 * KSu + lc41 * 4, kp1, vp1);
        }
        __syncthreads();
    }

    // ---- Epilogue: normalize, store (output [B, H, L, D]) ----
    float* Og = O + ((size_t)(b * Hc + h) * Lc + (size_t)m * BM) * Dc;
    float invA = 1.f / lA, invB = 1.f / lB;
#pragma unroll
    for (int j = 0; j < 8; ++j) {
        int c = 8 * j + 2 * tg;
        *(float2*)(Og + (size_t)(R0 + g)     * Dc + c) = make_float2(o[j][0] * invA, o[j][1] * invA);
        *(float2*)(Og + (size_t)(R0 + g + 8) * Dc + c) = make_float2(o[j][2] * invB, o[j][3] * invB);
    }
}

extern "C" void kernel_launch(void* const* d_in, const int* in_sizes, int n_in,
                              void* d_out, int out_size) {
    const float* Q = (const float*)d_in[0];
    const float* K = (const float*)d_in[1];
    const float* V = (const float*)d_in[2];
    float* O = (float*)d_out;

    cudaFuncSetAttribute(logsparse_flash_tc8_kernel,
                         cudaFuncAttributeMaxDynamicSharedMemorySize, SMEM_BYTES);

    dim3 grid(Lc / BM, Bc * Hc);
    logsparse_flash_tc8_kernel<<<grid, NT, SMEM_BYTES>>>(Q, K, V, O);
}

// round 9
// speedup vs baseline: 1.4167x; 1.4167x over previous
#include <cuda_runtime.h>
#include <cstdint>

// Problem constants (B=4, L=2048, H=16, D=64 — fixed by the dataset)
#define Bc 4
#define Hc 16
#define Lc 2048
#define Dc 64
#define BM 128
#define BN 64
#define NT 256
#define NW 8

// Smem:
//   Kb : uint2[64 key][KS2 grp]  grp=(d/2): (bf16x2 hi pair, bf16x2 lo pair)
//   VH : uint2[64 key][KSu d]    (tf32 hi,lo pairs)
//   P  : per-warp float[16][PSf]
#define KS2 36
#define KSu 68
#define PSf 68
#define SMEM_BYTES (64 * KS2 * 8 + 64 * KSu * 8 + NW * 16 * PSf * 4)  // 88,064 B

__device__ __forceinline__ void tf32_split(float x, uint32_t& hi, uint32_t& lo) {
    uint32_t h;
    asm("cvt.rna.tf32.f32 %0, %1;" : "=r"(h) : "f"(x));
    hi = h;
    float lf = x - __uint_as_float(h);
    asm("cvt.rna.tf32.f32 %0, %1;" : "=r"(lo) : "f"(lf));
}
__device__ __forceinline__ uint32_t tf32_rna(float x) {
    uint32_t h;
    asm("cvt.rna.tf32.f32 %0, %1;" : "=r"(h) : "f"(x));
    return h;
}
// Pack (lo, hi) floats into bf16x2 (lo -> lower half)
__device__ __forceinline__ uint32_t bf2(float lo, float hi) {
    uint32_t r;
    asm("cvt.rn.bf16x2.f32 %0, %1, %2;" : "=r"(r) : "f"(hi), "f"(lo));
    return r;
}
// Split a float pair into bf16 hi-pair and lo-pair (residual)
__device__ __forceinline__ void bf16_split2(float x0, float x1,
                                            uint32_t& ph, uint32_t& pl) {
    ph = bf2(x0, x1);
    float h0 = __uint_as_float(ph << 16);
    float h1 = __uint_as_float(ph & 0xFFFF0000u);
    pl = bf2(x0 - h0, x1 - h1);
}
// tf32 m16n8k8
__device__ __forceinline__ void mma8(float* d,
                                     uint32_t a0, uint32_t a1, uint32_t a2, uint32_t a3,
                                     uint32_t b0, uint32_t b1) {
    asm("mma.sync.aligned.m16n8k8.row.col.f32.tf32.tf32.f32 "
        "{%0,%1,%2,%3},{%4,%5,%6,%7},{%8,%9},{%0,%1,%2,%3};"
        : "+f"(d[0]), "+f"(d[1]), "+f"(d[2]), "+f"(d[3])
        : "r"(a0), "r"(a1), "r"(a2), "r"(a3), "r"(b0), "r"(b1));
}
// bf16 m16n8k16
__device__ __forceinline__ void mma16(float* d,
                                      uint32_t a0, uint32_t a1, uint32_t a2, uint32_t a3,
                                      uint32_t b0, uint32_t b1) {
    asm("mma.sync.aligned.m16n8k16.row.col.f32.bf16.bf16.f32 "
        "{%0,%1,%2,%3},{%4,%5,%6,%7},{%8,%9},{%0,%1,%2,%3};"
        : "+f"(d[0]), "+f"(d[1]), "+f"(d[2]), "+f"(d[3])
        : "r"(a0), "r"(a1), "r"(a2), "r"(a3), "r"(b0), "r"(b1));
}

__global__ void __launch_bounds__(NT, 2)
logsparse_flash_tc9_kernel(const float* __restrict__ Q,
                           const float* __restrict__ K,
                           const float* __restrict__ V,
                           float* __restrict__ O) {
    extern __shared__ char smc[];
    uint2* Kb = (uint2*)smc;                 // [64 key][KS2 grp] bf16 (hi2, lo2)
    uint2* VH = Kb + 64 * KS2;               // [64 key][KSu d]   tf32 (hi, lo)
    float* Pa = (float*)(VH + 64 * KSu);     // NW x [16][PSf]

    // Heavy blocks (large m) first: flatten triangular imbalance.
    const int m  = (int)gridDim.x - 1 - (int)blockIdx.x;
    const int bh = blockIdx.y;
    const int b  = bh >> 4;
    const int h  = bh & 15;

    const int tid  = threadIdx.x;
    const int wid  = tid >> 5;
    const int lane = tid & 31;
    const int g    = lane >> 2;
    const int tg   = lane & 3;

    float* Pw = Pa + wid * (16 * PSf);
    const int R0      = wid * 16;
    const int gRowA   = m * BM + R0 + g;
    const int gRowB   = gRowA + 8;
    const int wRowMax = m * BM + R0 + 15;    // lane-uniform warp row bound

    const size_t rs = (size_t)Hc * Dc;       // 1024 floats between seq positions
    const float* Qg = Q + ((size_t)b * Lc + (size_t)m * BM) * rs + (size_t)h * Dc;
    const float* Kg = K + (size_t)b * Lc * rs + (size_t)h * Dc;
    const float* Vg = V + (size_t)b * Lc * rs + (size_t)h * Dc;

    // ---- Q fragments once: bf16 hi/lo pairs, pre-scaled by log2(e) ----
    // m16n8k16 A layout: a0=A[g][2tg,2tg+1], a1=A[g+8][..], a2=A[g][2tg+8,+9], a3=A[g+8][..]
    const float LOG2E = 1.4426950408889634f;
    uint32_t qh[4][4], ql[4][4];
#pragma unroll
    for (int cc = 0; cc < 4; ++cc) {
        int k0 = 16 * cc + 2 * tg;
        const float* qrA = Qg + (size_t)(R0 + g) * rs;
        const float* qrB = Qg + (size_t)(R0 + g + 8) * rs;
        bf16_split2(qrA[k0]     * LOG2E, qrA[k0 + 1] * LOG2E, qh[cc][0], ql[cc][0]);
        bf16_split2(qrB[k0]     * LOG2E, qrB[k0 + 1] * LOG2E, qh[cc][1], ql[cc][1]);
        bf16_split2(qrA[k0 + 8] * LOG2E, qrA[k0 + 9] * LOG2E, qh[cc][2], ql[cc][2]);
        bf16_split2(qrB[k0 + 8] * LOG2E, qrB[k0 + 9] * LOG2E, qh[cc][3], ql[cc][3]);
    }

    // ---- State (log2 domain) + O accumulators ----
    float o[8][4];
    float mA = -1e30f, mB = -1e30f, lA = 0.f, lB = 0.f;
#pragma unroll
    for (int j = 0; j < 8; ++j) { o[j][0] = o[j][1] = o[j][2] = o[j][3] = 0.f; }

    const int nend = (m * BM + BM - 1) / BN;    // 2m+1

    for (int n = 0; n <= nend; ++n) {
        __syncthreads();
        const int nBase = n * BN;
        // ---- Load K (bf16 hi/lo pack) and V (tf32 hi/lo) tiles ----
#pragma unroll
        for (int it = 0; it < 4; ++it) {
            int idx = tid + it * NT;       // 0..1023
            int r = idx >> 4, c4 = idx & 15;
            const size_t go = (size_t)(nBase + r) * rs + c4 * 4;
            float4 kv = *(const float4*)(Kg + go);
            float4 vv = *(const float4*)(Vg + go);
            // K: two (hi2, lo2) groups -> one uint4 store
            uint32_t h01, l01, h23, l23;
            bf16_split2(kv.x, kv.y, h01, l01);
            bf16_split2(kv.z, kv.w, h23, l23);
            *(uint4*)(Kb + r * KS2 + c4 * 2) = make_uint4(h01, l01, h23, l23);
            // V: tf32 split pairs
            uint2* vd = VH + r * KSu + c4 * 4;
            uint32_t hi, lo;
            tf32_split(vv.x, hi, lo); vd[0] = make_uint2(hi, lo);
            tf32_split(vv.y, hi, lo); vd[1] = make_uint2(hi, lo);
            tf32_split(vv.z, hi, lo); vd[2] = make_uint2(hi, lo);
            tf32_split(vv.w, hi, lo); vd[3] = make_uint2(hi, lo);
        }
        __syncthreads();

        if (nBase > wRowMax) continue;     // warp fully masked (uniform)

        // ---- S = Q K^T via 3xBF16 mma (hh + hl + lh) ----
        float s[8][4];
#pragma unroll
        for (int j = 0; j < 8; ++j) { s[j][0] = s[j][1] = s[j][2] = s[j][3] = 0.f; }

#pragma unroll
        for (int cc = 0; cc < 4; ++cc) {
#pragma unroll
            for (int j = 0; j < 8; ++j) {
                // B frag: key row 8j+g, k pairs at grp 8cc+tg and 8cc+tg+4
                uint2 b0 = Kb[(8 * j + g) * KS2 + 8 * cc + tg];
                uint2 b1 = Kb[(8 * j + g) * KS2 + 8 * cc + tg + 4];
                mma16(s[j], qh[cc][0], qh[cc][1], qh[cc][2], qh[cc][3], b0.x, b1.x);
                mma16(s[j], qh[cc][0], qh[cc][1], qh[cc][2], qh[cc][3], b0.y, b1.y);
                mma16(s[j], ql[cc][0], ql[cc][1], ql[cc][2], ql[cc][3], b0.x, b1.x);
            }
        }

        // ---- Causal mask (only blocks touching the diagonal) ----
        if (nBase + BN - 1 > m * BM + R0) {
#pragma unroll
            for (int j = 0; j < 8; ++j) {
                int c0 = nBase + 8 * j + 2 * tg;
                if (c0     > gRowA) s[j][0] = -1e30f;
                if (c0 + 1 > gRowA) s[j][1] = -1e30f;
                if (c0     > gRowB) s[j][2] = -1e30f;
                if (c0 + 1 > gRowB) s[j][3] = -1e30f;
            }
        }

        // ---- Online softmax (log2 domain), stage tf32-rounded P ----
        float tA = s[0][0], tB = s[0][2];
#pragma unroll
        for (int j = 0; j < 8; ++j) {
            tA = fmaxf(tA, fmaxf(s[j][0], s[j][1]));
            tB = fmaxf(tB, fmaxf(s[j][2], s[j][3]));
        }
        tA = fmaxf(tA, __shfl_xor_sync(0xffffffffu, tA, 1));
        tA = fmaxf(tA, __shfl_xor_sync(0xffffffffu, tA, 2));
        tB = fmaxf(tB, __shfl_xor_sync(0xffffffffu, tB, 1));
        tB = fmaxf(tB, __shfl_xor_sync(0xffffffffu, tB, 2));
        float mnA = fmaxf(mA, tA), mnB = fmaxf(mB, tB);
        float scA = exp2f(mA - mnA), scB = exp2f(mB - mnB);
        float rsA = 0.f, rsB = 0.f;
#pragma unroll
        for (int j = 0; j < 8; ++j) {
            // exp2, round to tf32 ONCE; rounded value feeds both the row-sum
            // and the PV mma, so normalization is self-consistent.
            uint32_t p0 = tf32_rna(exp2f(s[j][0] - mnA));
            uint32_t p1 = tf32_rna(exp2f(s[j][1] - mnA));
            uint32_t p2 = tf32_rna(exp2f(s[j][2] - mnB));
            uint32_t p3 = tf32_rna(exp2f(s[j][3] - mnB));
            rsA += __uint_as_float(p0) + __uint_as_float(p1);
            rsB += __uint_as_float(p2) + __uint_as_float(p3);
            int c = 8 * j + 2 * tg;
            *(float2*)(Pw + (g)     * PSf + c) =
                make_float2(__uint_as_float(p0), __uint_as_float(p1));
            *(float2*)(Pw + (g + 8) * PSf + c) =
                make_float2(__uint_as_float(p2), __uint_as_float(p3));
        }
        rsA += __shfl_xor_sync(0xffffffffu, rsA, 1);
        rsA += __shfl_xor_sync(0xffffffffu, rsA, 2);
        rsB += __shfl_xor_sync(0xffffffffu, rsB, 1);
        rsB += __shfl_xor_sync(0xffffffffu, rsB, 2);
        lA = lA * scA + rsA;  mA = mnA;
        lB = lB * scB + rsB;  mB = mnB;
#pragma unroll
        for (int j = 0; j < 8; ++j) {
            o[j][0] *= scA; o[j][1] *= scA;
            o[j][2] *= scB; o[j][3] *= scB;
        }
        __syncwarp();

        // ---- O += P V : tf32, 2 mma terms (P exact tf32, V hi+lo) ----
#pragma unroll
        for (int cc = 0; cc < 8; ++cc) {
            uint32_t a0 = __float_as_uint(Pw[(g)     * PSf + 8 * cc + tg]);
            uint32_t a1 = __float_as_uint(Pw[(g + 8) * PSf + 8 * cc + tg]);
            uint32_t a2 = __float_as_uint(Pw[(g)     * PSf + 8 * cc + tg + 4]);
            uint32_t a3 = __float_as_uint(Pw[(g + 8) * PSf + 8 * cc + tg + 4]);
#pragma unroll
            for (int j = 0; j < 8; ++j) {
                uint2 v0 = VH[(8 * cc + tg)     * KSu + 8 * j + g];
                uint2 v1 = VH[(8 * cc + tg + 4) * KSu + 8 * j + g];
                mma8(o[j], a0, a1, a2, a3, v0.x, v1.x);
                mma8(o[j], a0, a1, a2, a3, v0.y, v1.y);
            }
        }
    }

    // ---- Epilogue: normalize, store (output [B, H, L, D]) ----
    float* Og = O + ((size_t)(b * Hc + h) * Lc + (size_t)m * BM) * Dc;
    float invA = 1.f / lA, invB = 1.f / lB;
#pragma unroll
    for (int j = 0; j < 8; ++j) {
        int c = 8 * j + 2 * tg;
        *(float2*)(Og + (size_t)(R0 + g)     * Dc + c) = make_float2(o[j][0] * invA, o[j][1] * invA);
        *(float2*)(Og + (size_t)(R0 + g + 8) * Dc + c) = make_float2(o[j][2] * invB, o[j][3] * invB);
    }
}

extern "C" void kernel_launch(void* const* d_in, const int* in_sizes, int n_in,
                              void* d_out, int out_size) {
    const float* Q = (const float*)d_in[0];
    const float* K = (const float*)d_in[1];
    const float* V = (const float*)d_in[2];
    float* O = (float*)d_out;

    cudaFuncSetAttribute(logsparse_flash_tc9_kernel,
                         cudaFuncAttributeMaxDynamicSharedMemorySize, SMEM_BYTES);

    dim3 grid(Lc / BM, Bc * Hc);
    logsparse_flash_tc9_kernel<<<grid, NT, SMEM_BYTES>>>(Q, K, V, O);
}

// round 10
// speedup vs baseline: 1.7485x; 1.2342x over previous
#include <cuda_runtime.h>
#include <cstdint>

// Problem constants (B=4, L=2048, H=16, D=64 — fixed by the dataset)
#define Bc 4
#define Hc 16
#define Lc 2048
#define Dc 64
#define BM 128
#define BN 64
#define NT 256
#define NW 8

// Smem:
//   Kb : uint2[64 key][KS2 grp]   grp=(d/2): (bf16x2 hi pair, bf16x2 lo pair)
//   Vt : uint32[64 d][VTS key]    word = (bf16hi<<16)|bf16lo of V[key][d],
//        key slot swizzled by ((d&1)<<1) -> conflict-free LDS.64 fragments
#define KS2 36
#define VTS 72
#define SMEM_BYTES (64 * KS2 * 8 + 64 * VTS * 4)   // 36,864 B

// Pack (lo, hi) floats into bf16x2 (lo -> lower half)
__device__ __forceinline__ uint32_t bf2(float lo, float hi) {
    uint32_t r;
    asm("cvt.rn.bf16x2.f32 %0, %1, %2;" : "=r"(r) : "f"(hi), "f"(lo));
    return r;
}
// Split a float pair into bf16 hi-pair and lo-pair (residual)
__device__ __forceinline__ void bf16_split2(float x0, float x1,
                                            uint32_t& ph, uint32_t& pl) {
    ph = bf2(x0, x1);
    float h0 = __uint_as_float(ph << 16);
    float h1 = __uint_as_float(ph & 0xFFFF0000u);
    pl = bf2(x0 - h0, x1 - h1);
}
// Pack one float as (bf16hi << 16) | bf16lo(residual)
__device__ __forceinline__ uint32_t vpack(float v) {
    uint32_t t = bf2(v, v);
    float hf = __uint_as_float(t << 16);
    return bf2(v - hf, v);
}
__device__ __forceinline__ uint32_t prmt(uint32_t a, uint32_t b, uint32_t s) {
    uint32_t d;
    asm("prmt.b32 %0, %1, %2, %3;" : "=r"(d) : "r"(a), "r"(b), "r"(s));
    return d;
}
// bf16 m16n8k16
__device__ __forceinline__ void mma16(float* d,
                                      uint32_t a0, uint32_t a1, uint32_t a2, uint32_t a3,
                                      uint32_t b0, uint32_t b1) {
    asm("mma.sync.aligned.m16n8k16.row.col.f32.bf16.bf16.f32 "
        "{%0,%1,%2,%3},{%4,%5,%6,%7},{%8,%9},{%0,%1,%2,%3};"
        : "+f"(d[0]), "+f"(d[1]), "+f"(d[2]), "+f"(d[3])
        : "r"(a0), "r"(a1), "r"(a2), "r"(a3), "r"(b0), "r"(b1));
}

__global__ void __launch_bounds__(NT, 2)
logsparse_flash_tc10_kernel(const float* __restrict__ Q,
                            const float* __restrict__ K,
                            const float* __restrict__ V,
                            float* __restrict__ O) {
    extern __shared__ char smc[];
    uint2* Kb = (uint2*)smc;                 // [64 key][KS2 grp] bf16 (hi2, lo2)
    uint32_t* Vt = (uint32_t*)(Kb + 64 * KS2);  // [64 d][VTS key] (hi16|lo16)

    // Heavy blocks (large m) first: flatten triangular imbalance.
    const int m  = (int)gridDim.x - 1 - (int)blockIdx.x;
    const int bh = blockIdx.y;
    const int b  = bh >> 4;
    const int h  = bh & 15;

    const int tid  = threadIdx.x;
    const int wid  = tid >> 5;
    const int lane = tid & 31;
    const int g    = lane >> 2;
    const int tg   = lane & 3;

    const int R0      = wid * 16;
    const int gRowA   = m * BM + R0 + g;
    const int gRowB   = gRowA + 8;
    const int wRowMax = m * BM + R0 + 15;    // lane-uniform warp row bound

    const size_t rs = (size_t)Hc * Dc;       // 1024 floats between seq positions
    const float* Qg = Q + ((size_t)b * Lc + (size_t)m * BM) * rs + (size_t)h * Dc;
    const float* Kg = K + (size_t)b * Lc * rs + (size_t)h * Dc;
    const float* Vg = V + (size_t)b * Lc * rs + (size_t)h * Dc;

    // ---- Q fragments once: bf16 hi/lo pairs, pre-scaled by log2(e) ----
    const float LOG2E = 1.4426950408889634f;
    uint32_t qh[4][4], ql[4][4];
#pragma unroll
    for (int cc = 0; cc < 4; ++cc) {
        int k0 = 16 * cc + 2 * tg;
        const float* qrA = Qg + (size_t)(R0 + g) * rs;
        const float* qrB = Qg + (size_t)(R0 + g + 8) * rs;
        bf16_split2(qrA[k0]     * LOG2E, qrA[k0 + 1] * LOG2E, qh[cc][0], ql[cc][0]);
        bf16_split2(qrB[k0]     * LOG2E, qrB[k0 + 1] * LOG2E, qh[cc][1], ql[cc][1]);
        bf16_split2(qrA[k0 + 8] * LOG2E, qrA[k0 + 9] * LOG2E, qh[cc][2], ql[cc][2]);
        bf16_split2(qrB[k0 + 8] * LOG2E, qrB[k0 + 9] * LOG2E, qh[cc][3], ql[cc][3]);
    }

    // ---- State (log2 domain) + O accumulators ----
    float o[8][4];
    float mA = -1e30f, mB = -1e30f, lA = 0.f, lB = 0.f;
#pragma unroll
    for (int j = 0; j < 8; ++j) { o[j][0] = o[j][1] = o[j][2] = o[j][3] = 0.f; }

    const int nend = (m * BM + BM - 1) / BN;    // 2m+1

    for (int n = 0; n <= nend; ++n) {
        __syncthreads();
        const int nBase = n * BN;
        // ---- K tile: bf16 hi/lo pairs along d (as R9) ----
#pragma unroll
        for (int it = 0; it < 4; ++it) {
            int idx = tid + it * NT;       // 0..1023
            int r = idx >> 4, c4 = idx & 15;
            float4 kv = *(const float4*)(Kg + (size_t)(nBase + r) * rs + c4 * 4);
            uint32_t h01, l01, h23, l23;
            bf16_split2(kv.x, kv.y, h01, l01);
            bf16_split2(kv.z, kv.w, h23, l23);
            *(uint4*)(Kb + r * KS2 + c4 * 2) = make_uint4(h01, l01, h23, l23);
        }
        // ---- V tile: transposed [d][key], packed (hi|lo), swizzled ----
#pragma unroll
        for (int it = 0; it < 4; ++it) {
            int idx = tid + it * NT;       // 0..1023
            int d = idx & 63, kg = idx >> 6;
            const float* vp = Vg + (size_t)(nBase + 4 * kg) * rs + d;
            uint32_t w0 = vpack(vp[0]);
            uint32_t w1 = vpack(vp[rs]);
            uint32_t w2 = vpack(vp[2 * rs]);
            uint32_t w3 = vpack(vp[3 * rs]);
            uint4 st = (d & 1) ? make_uint4(w2, w3, w0, w1)
                               : make_uint4(w0, w1, w2, w3);
            *(uint4*)(Vt + d * VTS + 4 * kg) = st;
        }
        __syncthreads();

        if (nBase > wRowMax) continue;     // warp fully masked (uniform)

        // ---- S = Q K^T via 3xBF16 mma (hh + hl + lh) ----
        float s[8][4];
#pragma unroll
        for (int j = 0; j < 8; ++j) { s[j][0] = s[j][1] = s[j][2] = s[j][3] = 0.f; }

#pragma unroll
        for (int cc = 0; cc < 4; ++cc) {
#pragma unroll
            for (int j = 0; j < 8; ++j) {
                uint2 b0 = Kb[(8 * j + g) * KS2 + 8 * cc + tg];
                uint2 b1 = Kb[(8 * j + g) * KS2 + 8 * cc + tg + 4];
                mma16(s[j], qh[cc][0], qh[cc][1], qh[cc][2], qh[cc][3], b0.x, b1.x);
                mma16(s[j], qh[cc][0], qh[cc][1], qh[cc][2], qh[cc][3], b0.y, b1.y);
                mma16(s[j], ql[cc][0], ql[cc][1], ql[cc][2], ql[cc][3], b0.x, b1.x);
            }
        }

        // ---- Causal mask (only blocks touching the diagonal) ----
        if (nBase + BN - 1 > m * BM + R0) {
#pragma unroll
            for (int j = 0; j < 8; ++j) {
                int c0 = nBase + 8 * j + 2 * tg;
                if (c0     > gRowA) s[j][0] = -1e30f;
                if (c0 + 1 > gRowA) s[j][1] = -1e30f;
                if (c0     > gRowB) s[j][2] = -1e30f;
                if (c0 + 1 > gRowB) s[j][3] = -1e30f;
            }
        }

        // ---- Online softmax (log2 domain) ----
        float tA = s[0][0], tB = s[0][2];
#pragma unroll
        for (int j = 0; j < 8; ++j) {
            tA = fmaxf(tA, fmaxf(s[j][0], s[j][1]));
            tB = fmaxf(tB, fmaxf(s[j][2], s[j][3]));
        }
        tA = fmaxf(tA, __shfl_xor_sync(0xffffffffu, tA, 1));
        tA = fmaxf(tA, __shfl_xor_sync(0xffffffffu, tA, 2));
        tB = fmaxf(tB, __shfl_xor_sync(0xffffffffu, tB, 1));
        tB = fmaxf(tB, __shfl_xor_sync(0xffffffffu, tB, 2));
        float mnA = fmaxf(mA, tA), mnB = fmaxf(mB, tB);
        float scA = exp2f(mA - mnA), scB = exp2f(mB - mnB);
        float rsA = 0.f, rsB = 0.f;
#pragma unroll
        for (int j = 0; j < 8; ++j) {
            s[j][0] = exp2f(s[j][0] - mnA);
            s[j][1] = exp2f(s[j][1] - mnA);
            s[j][2] = exp2f(s[j][2] - mnB);
            s[j][3] = exp2f(s[j][3] - mnB);
            rsA += s[j][0] + s[j][1];
            rsB += s[j][2] + s[j][3];
        }
        rsA += __shfl_xor_sync(0xffffffffu, rsA, 1);
        rsA += __shfl_xor_sync(0xffffffffu, rsA, 2);
        rsB += __shfl_xor_sync(0xffffffffu, rsB, 1);
        rsB += __shfl_xor_sync(0xffffffffu, rsB, 2);
        lA = lA * scA + rsA;  mA = mnA;
        lB = lB * scB + rsB;  mB = mnB;
#pragma unroll
        for (int j = 0; j < 8; ++j) {
            o[j][0] *= scA; o[j][1] *= scA;
            o[j][2] *= scB; o[j][3] *= scB;
        }

        // ---- Pack P to bf16 hi/lo A-fragments (straight from C-frag regs) ----
        uint32_t pa[4][4], pl_[4][4];
#pragma unroll
        for (int cc = 0; cc < 4; ++cc) {
            bf16_split2(s[2 * cc][0],     s[2 * cc][1],     pa[cc][0], pl_[cc][0]);
            bf16_split2(s[2 * cc][2],     s[2 * cc][3],     pa[cc][1], pl_[cc][1]);
            bf16_split2(s[2 * cc + 1][0], s[2 * cc + 1][1], pa[cc][2], pl_[cc][2]);
            bf16_split2(s[2 * cc + 1][2], s[2 * cc + 1][3], pa[cc][3], pl_[cc][3]);
        }

        // ---- O += P V : 3xBF16 (ph*vh + ph*vl + pl*vh), V from Vt ----
        const uint32_t sw = (g & 1) << 1;
#pragma unroll
        for (int cc = 0; cc < 4; ++cc) {
            const int kb = 16 * cc + 2 * tg;
#pragma unroll
            for (int j = 0; j < 8; ++j) {
                const uint32_t* vr = Vt + (8 * j + g) * VTS;
                uint2 u0 = *(const uint2*)(vr + ((kb)     ^ sw));
                uint2 u1 = *(const uint2*)(vr + ((kb + 8) ^ sw));
                uint32_t bh0 = prmt(u0.x, u0.y, 0x7632u);
                uint32_t bl0 = prmt(u0.x, u0.y, 0x5410u);
                uint32_t bh1 = prmt(u1.x, u1.y, 0x7632u);
                uint32_t bl1 = prmt(u1.x, u1.y, 0x5410u);
                mma16(o[j], pa[cc][0], pa[cc][1], pa[cc][2], pa[cc][3], bh0, bh1);
                mma16(o[j], pa[cc][0], pa[cc][1], pa[cc][2], pa[cc][3], bl0, bl1);
                mma16(o[j], pl_[cc][0], pl_[cc][1], pl_[cc][2], pl_[cc][3], bh0, bh1);
            }
        }
    }

    // ---- Epilogue: normalize, store (output [B, H, L, D]) ----
    float* Og = O + ((size_t)(b * Hc + h) * Lc + (size_t)m * BM) * Dc;
    float invA = 1.f / lA, invB = 1.f / lB;
#pragma unroll
    for (int j = 0; j < 8; ++j) {
        int c = 8 * j + 2 * tg;
        *(float2*)(Og + (size_t)(R0 + g)     * Dc + c) = make_float2(o[j][0] * invA, o[j][1] * invA);
        *(float2*)(Og + (size_t)(R0 + g + 8) * Dc + c) = make_float2(o[j][2] * invB, o[j][3] * invB);
    }
}

extern "C" void kernel_launch(void* const* d_in, const int* in_sizes, int n_in,
                              void* d_out, int out_size) {
    const float* Q = (const float*)d_in[0];
    const float* K = (const float*)d_in[1];
    const float* V = (const float*)d_in[2];
    float* O = (float*)d_out;

    cudaFuncSetAttribute(logsparse_flash_tc10_kernel,
                         cudaFuncAttributeMaxDynamicSharedMemorySize, SMEM_BYTES);

    dim3 grid(Lc / BM, Bc * Hc);
    logsparse_flash_tc10_kernel<<<grid, NT, SMEM_BYTES>>>(Q, K, V, O);
}